// round 8
// baseline (speedup 1.0000x reference)
#include <cuda_runtime.h>

#define W    512
#define NIMG 32
#define CH   8

// Scratch: filtered projections transposed to [n][angle][r]
__device__ __align__(16) float g_proj[(size_t)NIMG * W * W];
// Ramp-filter spatial taps, rearranged: g_hh[i] = h[(i-511) mod 1024], i in [0,1022]
__device__ float g_hh[1024];
// Per-angle (cos*255.5, sin*255.5)
__device__ float2 g_cs[W];

// ---------------------------------------------------------------------------
// K0: taps. h[m] = (1/1024) * sum_k filt[k] * cos(2*pi*k*m/1024),
// filt[k] = min(k,1024-k)/512. Integer phase reduction + cospif + double acc.
// ---------------------------------------------------------------------------
__global__ void k_hh() {
    int i = blockIdx.x * blockDim.x + threadIdx.x;
    if (i >= 1024) return;
    if (i == 1023) { g_hh[1023] = 0.0f; return; }
    int m2 = (i + 513) & 1023;                    // (i-511) mod 1024
    double s = 0.0;
    for (int k = 0; k < 1024; ++k) {
        int mn = (k < 512) ? k : (1024 - k);
        float f = (float)mn * (1.0f / 512.0f);    // filt[k]
        int ph = (k * m2) & 1023;                 // exact integer phase
        s += (double)f * (double)cospif((float)ph * (1.0f / 512.0f));
    }
    g_hh[i] = (float)(s / 1024.0);
}

__global__ void k_trig(const float* __restrict__ theta) {
    int l = threadIdx.x;
    if (l < W) {
        float frac = theta[l] * (1.0f / 180.0f);
        g_cs[l] = make_float2(cospif(frac) * 255.5f, sinpif(frac) * 255.5f);
    }
}

// ---------------------------------------------------------------------------
// K1: ramp filter as Toeplitz GEMM, output transposed:
//   g_proj[n][l][r] = sum_{m=0}^{511} x[n][m][l] * hh[r - m + 511]
// 256 threads, tile 128 l x 128 r, micro-tile 8l x 8r, packed fma.rn.f32x2.
// ---------------------------------------------------------------------------
__global__ __launch_bounds__(256) void k_filter(const float* __restrict__ x) {
    __shared__ __align__(16) float2 hh2[1023];  // hh2[i] = (hh[i], hh[i+1])
    __shared__ __align__(16) float  As[16][128];
    const int tid = threadIdx.x;
    const int n     = blockIdx.z;
    const int rBase = blockIdx.x * 128;
    const int lBase = blockIdx.y * 128;

    for (int i = tid; i < 1023; i += 256)
        hh2[i] = make_float2(g_hh[i], g_hh[i + 1]);

    const int tx = tid & 15;          // l lane (strided by 16)
    const int ty = tid >> 4;          // r group (8 consecutive r)
    const int r0 = rBase + ty * 8;

    unsigned long long acc[8][4];     // [sl][pair]: pair p = (r0+2p, r0+2p+1)
#pragma unroll
    for (int sl = 0; sl < 8; ++sl)
#pragma unroll
        for (int p = 0; p < 4; ++p) acc[sl][p] = 0ull;

    const float* xn = x + (size_t)n * W * W;
    const int lrow = tid >> 5;        // 0..7
    const int c4   = (tid & 31) << 2; // 0..124

    for (int mc = 0; mc < 32; ++mc) {
        __syncthreads();
        const float* src = xn + (size_t)(mc * 16) * W + lBase;
        *(float4*)&As[lrow][c4]     = *(const float4*)(src + (size_t)lrow * W + c4);
        *(float4*)&As[lrow + 8][c4] = *(const float4*)(src + (size_t)(lrow + 8) * W + c4);
        __syncthreads();
#pragma unroll
        for (int mm = 0; mm < 16; ++mm) {
            const int hb = 511 + r0 - (mc * 16 + mm);
            unsigned long long h2[4];
#pragma unroll
            for (int p = 0; p < 4; ++p)
                h2[p] = *(const unsigned long long*)(&hh2[hb + 2 * p]);
#pragma unroll
            for (int sl = 0; sl < 8; ++sl) {
                float a = As[mm][tx + 16 * sl];
                unsigned long long a2;
                asm("mov.b64 %0, {%1, %1};" : "=l"(a2) : "r"(__float_as_uint(a)));
#pragma unroll
                for (int p = 0; p < 4; ++p)
                    asm("fma.rn.f32x2 %0, %1, %2, %0;"
                        : "+l"(acc[sl][p]) : "l"(a2), "l"(h2[p]));
            }
        }
    }

#pragma unroll
    for (int sl = 0; sl < 8; ++sl) {
        const int l = lBase + tx + 16 * sl;
        float v[8];
#pragma unroll
        for (int p = 0; p < 4; ++p) {
            unsigned int lo, hi;
            asm("mov.b64 {%0, %1}, %2;" : "=r"(lo), "=r"(hi) : "l"(acc[sl][p]));
            v[2 * p]     = __uint_as_float(lo);
            v[2 * p + 1] = __uint_as_float(hi);
        }
        float* dst = g_proj + ((size_t)n * W + l) * W + r0;
        *(float4*)dst       = make_float4(v[0], v[1], v[2], v[3]);
        *(float4*)(dst + 4) = make_float4(v[4], v[5], v[6], v[7]);
    }
}

// ---------------------------------------------------------------------------
// K2: backprojection. Block = 512 threads = 16 rows x (32 lanes), grid (32,32).
// Thread: row i, 16 pixels at j = lane + 32u. Prebaked lerp pairs in smem:
//   v = a[k] + ry*d[k],  a = p[k] - k*(p[k+1]-p[k]),  d = p[k+1]-p[k]
// Floor + index via add.rm magic number. Lane-adjacent j keeps smem banks
// conflict-free for all angles.
// ---------------------------------------------------------------------------
__global__ __launch_bounds__(512) void k_backproj(float* __restrict__ out) {
    __shared__ __align__(16) float  raw[CH][W];
    __shared__ __align__(16) float2 pairs[CH][W];
    const int tid    = threadIdx.x;
    const int n      = blockIdx.y;
    const int i      = blockIdx.x * 16 + (tid >> 5);
    const int lane   = tid & 31;
    const float STEP = 2.0f / 511.0f;
    const float ti   = fmaf((float)i, STEP, -1.0f);

    float tjv[16], acc[16];
#pragma unroll
    for (int u = 0; u < 16; ++u) {
        tjv[u] = fmaf((float)(lane + 32 * u), STEP, -1.0f);
        acc[u] = 0.0f;
    }

    const float* projn = g_proj + (size_t)n * W * W;

    for (int lc = 0; lc < W / CH; ++lc) {
        __syncthreads();
        {   // stage CH angle rows: CH*W/4 = 1024 float4, 2 per thread
            const float4* src  = (const float4*)(projn + (size_t)lc * CH * W);
            float4*       dstv = (float4*)&raw[0][0];
#pragma unroll
            for (int v = 0; v < (CH * W / 4) / 512; ++v) {
                int e = tid + v * 512;
                dstv[e] = src[e];
            }
        }
        __syncthreads();
#pragma unroll
        for (int v = 0; v < (CH * W) / 512; ++v) {
            int e = tid + v * 512;
            int l = e >> 9;
            int k = e & (W - 1);
            float p0 = raw[l][k];
            float a, d;
            if (k < W - 1) {
                d = raw[l][k + 1] - p0;
                a = fmaf(-(float)k, d, p0);
            } else { a = p0; d = 0.0f; }
            pairs[l][k] = make_float2(a, d);
        }
        __syncthreads();
#pragma unroll 1
        for (int a8 = 0; a8 < CH; ++a8) {
            float2 cs   = g_cs[lc * CH + a8];
            float  cB   = cs.x;
            float  rowB = fmaf(-ti, cs.y, 255.5f);
            const float2* P = pairs[a8];
#pragma unroll
            for (int u = 0; u < 16; ++u) {
                float ry = fmaf(tjv[u], cB, rowB);
                ry = fminf(fmaxf(ry, 0.0f), 511.0f);
                float big;
                asm("add.rm.f32 %0, %1, %2;" : "=f"(big) : "f"(ry), "f"(8388608.0f));
                int idx = __float_as_int(big) & 1023;   // = floor(ry)
                float2 pd = P[idx];
                acc[u] = fmaf(ry, pd.y, acc[u] + pd.x);
            }
        }
    }

    const float scale = (float)(3.14159265358979323846 / 1024.0); // pi/(2L)
    const float ti2 = ti * ti;
    float* orow = out + ((size_t)n * W + i) * W;
#pragma unroll
    for (int u = 0; u < 16; ++u) {
        float tj = tjv[u];
        orow[lane + 32 * u] = (ti2 + tj * tj <= 1.0f) ? acc[u] * scale : 0.0f;
    }
}

extern "C" void kernel_launch(void* const* d_in, const int* in_sizes, int n_in,
                              void* d_out, int out_size) {
    const float* x     = (const float*)d_in[0];
    const float* theta = (const float*)d_in[1];
    if (n_in >= 2 && in_sizes[0] == W && in_sizes[1] != W) { // defensive order swap
        x = (const float*)d_in[1];
        theta = (const float*)d_in[0];
    }
    float* out = (float*)d_out;

    k_hh<<<2, 512>>>();
    k_trig<<<1, 512>>>(theta);

    dim3 g1(4, 4, NIMG);
    k_filter<<<g1, 256>>>(x);

    dim3 g2(32, NIMG);
    k_backproj<<<g2, 512>>>(out);
}

// round 9
// speedup vs baseline: 1.6169x; 1.6169x over previous
#include <cuda_runtime.h>

#define W    512
#define NIMG 32
#define CH   8
#define PW   768   // padded pairs width: biased index range [22, 744] fits

// Scratch: filtered projections transposed to [n][angle][r]
__device__ __align__(16) float g_proj[(size_t)NIMG * W * W];
// Ramp-filter spatial taps, rearranged: g_hh[i] = h[(i-511) mod 1024], i in [0,1022]
__device__ float g_hh[1024];
// Per-angle (cos*255.5, sin*255.5)
__device__ float2 g_cs[W];

// ---------------------------------------------------------------------------
// K0: taps. h[m] = (1/1024) * sum_k filt[k] * cos(2*pi*k*m/1024),
// filt[k] = min(k,1024-k)/512. One block per tap, 256-thread double reduction.
// ---------------------------------------------------------------------------
__global__ __launch_bounds__(256) void k_hh() {
    __shared__ double red[256];
    const int i = blockIdx.x;
    const int t = threadIdx.x;
    if (i == 1023) { if (t == 0) g_hh[1023] = 0.0f; return; }
    const int m2 = (i + 513) & 1023;              // (i-511) mod 1024
    double s = 0.0;
    for (int k = t; k < 1024; k += 256) {
        int mn = (k < 512) ? k : (1024 - k);
        float f = (float)mn * (1.0f / 512.0f);    // filt[k]
        int ph = (k * m2) & 1023;                 // exact integer phase
        s += (double)f * (double)cospif((float)ph * (1.0f / 512.0f));
    }
    red[t] = s;
    __syncthreads();
    for (int st = 128; st > 0; st >>= 1) {
        if (t < st) red[t] += red[t + st];
        __syncthreads();
    }
    if (t == 0) g_hh[i] = (float)(red[0] / 1024.0);
}

__global__ void k_trig(const float* __restrict__ theta) {
    int l = threadIdx.x;
    if (l < W) {
        float frac = theta[l] * (1.0f / 180.0f);
        g_cs[l] = make_float2(cospif(frac) * 255.5f, sinpif(frac) * 255.5f);
    }
}

// ---------------------------------------------------------------------------
// K1: ramp filter as Toeplitz GEMM, output transposed:
//   g_proj[n][l][r] = sum_{m=0}^{511} x[n][m][l] * hh[r - m + 511]
// 256 threads, tile 128 l x 128 r, micro-tile 8l x 8r, packed fma.rn.f32x2.
// ---------------------------------------------------------------------------
__global__ __launch_bounds__(256) void k_filter(const float* __restrict__ x) {
    __shared__ __align__(16) float2 hh2[1023];  // hh2[i] = (hh[i], hh[i+1])
    __shared__ __align__(16) float  As[16][128];
    const int tid = threadIdx.x;
    const int n     = blockIdx.z;
    const int rBase = blockIdx.x * 128;
    const int lBase = blockIdx.y * 128;

    for (int i = tid; i < 1023; i += 256)
        hh2[i] = make_float2(g_hh[i], g_hh[i + 1]);

    const int tx = tid & 15;          // l lane (strided by 16)
    const int ty = tid >> 4;          // r group (8 consecutive r)
    const int r0 = rBase + ty * 8;

    unsigned long long acc[8][4];     // [sl][pair]: pair p = (r0+2p, r0+2p+1)
#pragma unroll
    for (int sl = 0; sl < 8; ++sl)
#pragma unroll
        for (int p = 0; p < 4; ++p) acc[sl][p] = 0ull;

    const float* xn = x + (size_t)n * W * W;
    const int lrow = tid >> 5;        // 0..7
    const int c4   = (tid & 31) << 2; // 0..124

    for (int mc = 0; mc < 32; ++mc) {
        __syncthreads();
        const float* src = xn + (size_t)(mc * 16) * W + lBase;
        *(float4*)&As[lrow][c4]     = *(const float4*)(src + (size_t)lrow * W + c4);
        *(float4*)&As[lrow + 8][c4] = *(const float4*)(src + (size_t)(lrow + 8) * W + c4);
        __syncthreads();
#pragma unroll
        for (int mm = 0; mm < 16; ++mm) {
            const int hb = 511 + r0 - (mc * 16 + mm);
            unsigned long long h2[4];
#pragma unroll
            for (int p = 0; p < 4; ++p)
                h2[p] = *(const unsigned long long*)(&hh2[hb + 2 * p]);
#pragma unroll
            for (int sl = 0; sl < 8; ++sl) {
                float a = As[mm][tx + 16 * sl];
                unsigned long long a2;
                asm("mov.b64 %0, {%1, %1};" : "=l"(a2) : "r"(__float_as_uint(a)));
#pragma unroll
                for (int p = 0; p < 4; ++p)
                    asm("fma.rn.f32x2 %0, %1, %2, %0;"
                        : "+l"(acc[sl][p]) : "l"(a2), "l"(h2[p]));
            }
        }
    }

#pragma unroll
    for (int sl = 0; sl < 8; ++sl) {
        const int l = lBase + tx + 16 * sl;
        float v[8];
#pragma unroll
        for (int p = 0; p < 4; ++p) {
            unsigned int lo, hi;
            asm("mov.b64 {%0, %1}, %2;" : "=r"(lo), "=r"(hi) : "l"(acc[sl][p]));
            v[2 * p]     = __uint_as_float(lo);
            v[2 * p + 1] = __uint_as_float(hi);
        }
        float* dst = g_proj + ((size_t)n * W + l) * W + r0;
        *(float4*)dst       = make_float4(v[0], v[1], v[2], v[3]);
        *(float4*)(dst + 4) = make_float4(v[4], v[5], v[6], v[7]);
    }
}

// ---------------------------------------------------------------------------
// K2: backprojection. Block = 512 threads = 16 rows x 32 lanes, grid (32,32).
// Thread: row i, 16 pixels at j = lane + 32u (bank-conflict-free for all
// angles: adjacent lanes -> adjacent/broadcast smem words).
// Biased coordinate ryb = ry + 128 in [22.1, 744.9] (always positive, no
// clamps needed). Pair table per angle has 768 entries; [0,128) and
// (639,768) are zeros (only out-of-circle pixels land there; the circle
// mask discards them). Stored pairs are pre-biased:
//   pairs[k+128] = (a', d),  a' = p_k - (k+128)*d,  d = p_{k+1}-p_k
// so the lerp is v = a' + ryb*d.
// Index via 2^20 magic: mantissa of (ryb + 2^20) is floor(8*ryb) under
// round-down, so (bits & 0x1FF8) is the byte offset of pairs[floor(ryb)].
// Per inner op: FFMA(ryb) + FADD.RM + LOP3 + LDS.64 + FADD + FFMA.
// ---------------------------------------------------------------------------
__global__ __launch_bounds__(512) void k_backproj(float* __restrict__ out) {
    __shared__ __align__(16) float  raw[CH][W];
    __shared__ __align__(16) float2 pairs[CH][PW];
    const int tid    = threadIdx.x;
    const int n      = blockIdx.y;
    const int i      = blockIdx.x * 16 + (tid >> 5);
    const int lane   = tid & 31;
    const float STEP = 2.0f / 511.0f;
    const float ti   = fmaf((float)i, STEP, -1.0f);

    // Zero guard regions of the pair table once (data region [128,640) is
    // rewritten every chunk; guards stay zero).
    {
        float2* pz = &pairs[0][0];
        for (int e = tid; e < CH * PW; e += 512) pz[e] = make_float2(0.0f, 0.0f);
    }

    float tjv[16], acc[16];
#pragma unroll
    for (int u = 0; u < 16; ++u) {
        tjv[u] = fmaf((float)(lane + 32 * u), STEP, -1.0f);
        acc[u] = 0.0f;
    }

    const float* projn = g_proj + (size_t)n * W * W;

    for (int lc = 0; lc < W / CH; ++lc) {
        __syncthreads();
        {   // stage CH angle rows: CH*W/4 = 1024 float4, 2 per thread
            const float4* src  = (const float4*)(projn + (size_t)lc * CH * W);
            float4*       dstv = (float4*)&raw[0][0];
#pragma unroll
            for (int v = 0; v < (CH * W / 4) / 512; ++v) {
                int e = tid + v * 512;
                dstv[e] = src[e];
            }
        }
        __syncthreads();
#pragma unroll
        for (int v = 0; v < (CH * W) / 512; ++v) {
            int e = tid + v * 512;
            int l = e >> 9;
            int k = e & (W - 1);
            float p0 = raw[l][k];
            float d = (k < W - 1) ? (raw[l][k + 1] - p0) : 0.0f;
            float a = fmaf(-(float)(k + 128), d, p0);
            pairs[l][k + 128] = make_float2(a, d);
        }
        __syncthreads();
#pragma unroll
        for (int a8 = 0; a8 < CH; ++a8) {
            const float2 cs   = g_cs[lc * CH + a8];
            const float  cB   = cs.x;
            const float  rowB = fmaf(-ti, cs.y, 383.5f);   // 255.5 + 128 bias
            const float2* Pa  = pairs[a8];
#pragma unroll
            for (int u = 0; u < 16; ++u) {
                float ryb = fmaf(tjv[u], cB, rowB);
                float big;
                asm("add.rm.f32 %0, %1, %2;" : "=f"(big) : "f"(ryb), "f"(1048576.0f));
                unsigned off = __float_as_uint(big) & 0x1FF8u;
                float2 pd = *reinterpret_cast<const float2*>(
                                reinterpret_cast<const char*>(Pa) + off);
                acc[u] = fmaf(ryb, pd.y, acc[u] + pd.x);
            }
        }
    }

    const float scale = (float)(3.14159265358979323846 / 1024.0); // pi/(2L)
    const float ti2 = ti * ti;
    float* orow = out + ((size_t)n * W + i) * W;
#pragma unroll
    for (int u = 0; u < 16; ++u) {
        float tj = tjv[u];
        orow[lane + 32 * u] = (ti2 + tj * tj <= 1.0f) ? acc[u] * scale : 0.0f;
    }
}

extern "C" void kernel_launch(void* const* d_in, const int* in_sizes, int n_in,
                              void* d_out, int out_size) {
    const float* x     = (const float*)d_in[0];
    const float* theta = (const float*)d_in[1];
    if (n_in >= 2 && in_sizes[0] == W && in_sizes[1] != W) { // defensive order swap
        x = (const float*)d_in[1];
        theta = (const float*)d_in[0];
    }
    float* out = (float*)d_out;

    k_hh<<<1024, 256>>>();
    k_trig<<<1, 512>>>(theta);

    dim3 g1(4, 4, NIMG);
    k_filter<<<g1, 256>>>(x);

    dim3 g2(32, NIMG);
    k_backproj<<<g2, 512>>>(out);
}